// round 1
// baseline (speedup 1.0000x reference)
#include <cuda_runtime.h>
#include <math.h>

#define NNODES 30000
#define DIM    128
#define TLINKS 3000
#define KNEG   75
#define GAMMA  1.0f
#define MAXSQ  50.0f
// float(1.0 + 1e-7) == 1.00000011920928955f (1 ulp above 1.0f)
#define THETA0 (1.0f + 1e-7f)

// ---- device scratch (no allocation allowed) ----
__device__ float g_partial[TLINKS];   // per-link main-path contribution
__device__ float g_D[TLINKS];         // per-link D = sqdist(l,r)+GAMMA
__device__ int   g_flags[2*TLINKS];   // per-query fallback flag (0/1)
__device__ float g_fb[2*TLINKS];      // per-query fallback contribution
__device__ int   g_is64;              // train_links dtype: 1 = int64, 0 = int32

// ---------------------------------------------------------------------------
__device__ __forceinline__ long long get_link(const void* links, int pos) {
    if (g_is64) return ((const long long*)links)[pos];
    return (long long)((const int*)links)[pos];
}

__device__ __forceinline__ float sqdist_from_mdot(float mdot, float cval, float Kv) {
    float th = fmaxf(-mdot * cval, THETA0);
    float a  = acoshf(th);
    return fminf(Kv * a * a, MAXSQ);
}

// full 128-dim Minkowski sqdist, one thread does the whole dot (fallback path)
__device__ __forceinline__ float sqdist_full(const float* __restrict__ q,
                                             const float* __restrict__ row,
                                             float cval, float Kv) {
    float md = 0.f;
#pragma unroll
    for (int d = 0; d < DIM; d++) {
        float p = q[d] * row[d];
        md += (d == 0) ? -p : p;
    }
    return sqdist_from_mdot(md, cval, Kv);
}

// ---------------------------------------------------------------------------
// Detect whether train_links is int64 or int32.
// Safe read window: first 6000 int32 words exist in either case.
// If int64 (values < 30000), every odd int32 word (high half) is 0.
__global__ void detect_kernel(const int* __restrict__ links32) {
    int bad = 0;
    for (int i = threadIdx.x; i < TLINKS; i += blockDim.x)
        if (links32[2 * i + 1] != 0) bad = 1;
    int any_bad = __syncthreads_or(bad);
    if (threadIdx.x == 0) g_is64 = any_bad ? 0 : 1;
}

// ---------------------------------------------------------------------------
// Main kernel: one block per link. Computes D exactly, then for each of the
// two queries scans candidates in chunks of 128 (16 per warp), counting how
// many clip (theta <= 1+EPS  <=>  sqdist == S0 == global min). Early-exits
// once count >= 75: then the 75 smallest values are all exactly S0 and the
// contribution is 75 * relu(D - S0), independent of the dot products.
__global__ void __launch_bounds__(256) main_kernel(const float* __restrict__ emb,
                                                   const float* __restrict__ cptr,
                                                   const void*  __restrict__ links) {
    const int t    = blockIdx.x;
    const int tid  = threadIdx.x;
    const int w    = tid >> 5;
    const int lane = tid & 31;

    __shared__ float q[2][DIM];
    __shared__ float sD;
    __shared__ int   scnt;
    __shared__ int   wcnt[8];

    const float cval = cptr[0];
    const float Kv   = 1.0f / cval;

    const long long L = get_link(links, 2 * t);
    const long long R = get_link(links, 2 * t + 1);
    if (tid < 128) q[0][tid]       = emb[(size_t)L * DIM + tid];
    else           q[1][tid - 128] = emb[(size_t)R * DIM + (tid - 128)];
    __syncthreads();

    // D (warp 0), exact fp32
    if (w == 0) {
        float s = 0.f;
#pragma unroll
        for (int i = 0; i < 4; i++) {
            int d   = i * 32 + lane;
            float p = q[0][d] * q[1][d];
            s += (d == 0) ? -p : p;
        }
#pragma unroll
        for (int o = 16; o > 0; o >>= 1) s += __shfl_down_sync(0xffffffffu, s, o);
        if (lane == 0) sD = sqdist_from_mdot(s, cval, Kv) + GAMMA;
    }
    __syncthreads();
    const float D = sD;

    float a0 = acoshf(THETA0);
    const float S0 = fminf(Kv * a0 * a0, MAXSQ);

    float contrib = 0.f;

    for (int qi = 0; qi < 2; qi++) {
        __syncthreads();
        if (tid == 0) scnt = 0;
        __syncthreads();

        const float* qq = q[qi];
        int cnt  = 0;
        int base = 0;
        while (base < NNODES) {
            int local = 0;
#pragma unroll 4
            for (int jj = 0; jj < 16; jj++) {
                int j = base + w * 16 + jj;          // warp-uniform
                if (j < NNODES) {
                    const float* row = emb + (size_t)j * DIM;
                    float s = 0.f;
#pragma unroll
                    for (int i = 0; i < 4; i++) {
                        int d   = i * 32 + lane;
                        float p = qq[d] * row[d];
                        s += (d == 0) ? -p : p;
                    }
#pragma unroll
                    for (int o = 16; o > 0; o >>= 1)
                        s += __shfl_down_sync(0xffffffffu, s, o);
                    if (lane == 0 && (-s * cval) <= THETA0) local++;
                }
            }
            if (lane == 0) wcnt[w] = local;
            __syncthreads();
            if (tid == 0) {
                int c = scnt;
#pragma unroll
                for (int i = 0; i < 8; i++) c += wcnt[i];
                scnt = c;
            }
            __syncthreads();
            cnt  = scnt;                             // uniform
            base += 128;
            if (cnt >= KNEG) break;
        }

        if (cnt >= KNEG) {
            contrib += (float)KNEG * fmaxf(D - S0, 0.f);
            if (tid == 0) g_flags[qi * TLINKS + t] = 0;
        } else {
            if (tid == 0) g_flags[qi * TLINKS + t] = 1;
        }
    }

    if (tid == 0) {
        g_partial[t] = contrib;
        g_D[t]       = D;
    }
}

// ---------------------------------------------------------------------------
// Exact fallback: for a flagged query, radix-select (MSB-first, 8-bit digits)
// the 75th-smallest sqdist tau over all 30000 candidates, then sum
// relu(D - v) over values < tau plus (75 - m) copies at tau.
// sqdist >= 0 so float bit order == unsigned order. Deterministic reductions.
__global__ void __launch_bounds__(256) fallback_kernel(const float* __restrict__ emb,
                                                       const float* __restrict__ cptr,
                                                       const void*  __restrict__ links) {
    const int s   = blockIdx.x;
    const int tid = threadIdx.x;

    if (g_flags[s] == 0) {               // uniform over block
        if (tid == 0) g_fb[s] = 0.f;
        return;
    }

    const int t    = s % TLINKS;
    const int side = s / TLINKS;         // 0 = left query, 1 = right query

    __shared__ float        q[DIM];
    __shared__ unsigned int hist[256];
    __shared__ unsigned int s_prefix;
    __shared__ int          s_k;
    __shared__ double       ssum[256];
    __shared__ int          scm[256];

    const float cval = cptr[0];
    const float Kv   = 1.0f / cval;
    const long long node = get_link(links, 2 * t + side);

    if (tid < DIM) q[tid] = emb[(size_t)node * DIM + tid];
    if (tid == 0) { s_prefix = 0u; s_k = KNEG; }
    __syncthreads();

    const float D = g_D[t];

    for (int pass = 0; pass < 4; pass++) {
        const int shift = 24 - 8 * pass;
        const unsigned int pmask  = (pass == 0) ? 0u : (0xFFFFFFFFu << (shift + 8));
        const unsigned int prefix = s_prefix;
        hist[tid] = 0u;
        __syncthreads();
        for (int j = tid; j < NNODES; j += 256) {
            float v = sqdist_full(q, emb + (size_t)j * DIM, cval, Kv);
            unsigned int b = __float_as_uint(v);
            if ((b & pmask) == prefix)
                atomicAdd(&hist[(b >> shift) & 0xFFu], 1u);
        }
        __syncthreads();
        if (tid == 0) {
            int k = s_k;
            unsigned int acc = 0;
            int digit = 0;
            for (; digit < 255; digit++) {
                if (acc + hist[digit] >= (unsigned)k) break;
                acc += hist[digit];
            }
            s_k      = k - (int)acc;
            s_prefix = prefix | ((unsigned)digit << shift);
        }
        __syncthreads();
    }

    const unsigned int tau_bits = s_prefix;
    const float        tau      = __uint_as_float(tau_bits);

    int    m_local = 0;
    double sum_local = 0.0;
    for (int j = tid; j < NNODES; j += 256) {
        float v = sqdist_full(q, emb + (size_t)j * DIM, cval, Kv);
        if (__float_as_uint(v) < tau_bits) {
            m_local++;
            sum_local += (double)fmaxf(D - v, 0.f);
        }
    }
    ssum[tid] = sum_local;
    scm[tid]  = m_local;
    __syncthreads();
    for (int o = 128; o > 0; o >>= 1) {
        if (tid < o) { ssum[tid] += ssum[tid + o]; scm[tid] += scm[tid + o]; }
        __syncthreads();
    }
    if (tid == 0) {
        int m = scm[0];
        double total = ssum[0] + (double)(KNEG - m) * (double)fmaxf(D - tau, 0.f);
        g_fb[s] = (float)total;
    }
}

// ---------------------------------------------------------------------------
__global__ void finalize_kernel(float* __restrict__ out) {
    __shared__ double sh[256];
    const int tid = threadIdx.x;
    double s = 0.0;
    for (int i = tid; i < TLINKS;     i += 256) s += (double)g_partial[i];
    for (int i = tid; i < 2 * TLINKS; i += 256) s += (double)g_fb[i];
    sh[tid] = s;
    __syncthreads();
    for (int o = 128; o > 0; o >>= 1) {
        if (tid < o) sh[tid] += sh[tid + o];
        __syncthreads();
    }
    if (tid == 0)
        out[0] = (float)(sh[0] / (2.0 * (double)KNEG * (double)TLINKS));
}

// ---------------------------------------------------------------------------
extern "C" void kernel_launch(void* const* d_in, const int* in_sizes, int n_in,
                              void* d_out, int out_size) {
    const float* emb   = nullptr;
    const float* c     = nullptr;
    const void*  links = nullptr;
    for (int i = 0; i < n_in; i++) {
        if (in_sizes[i] == 1)                links = links; // placeholder
        if (in_sizes[i] == 1)                c     = (const float*)d_in[i];
        else if (in_sizes[i] == 2 * TLINKS)  links = d_in[i];
        else                                 emb   = (const float*)d_in[i];
    }

    detect_kernel  <<<1, 256>>>((const int*)links);
    main_kernel    <<<TLINKS, 256>>>(emb, c, links);
    fallback_kernel<<<2 * TLINKS, 256>>>(emb, c, links);
    finalize_kernel<<<1, 256>>>((float*)d_out);
}